// round 13
// baseline (speedup 1.0000x reference)
#include <cuda_runtime.h>
#include <cuda_fp16.h>
#include <cstdint>

// ======================= constants =======================
#define B_SZ   1024
#define LQ     16
#define LKV    128
#define DIM    512
#define NH     8
#define DH     64

#define MQ     (B_SZ*LQ)     // 16384
#define MKV    (B_SZ*LKV)    // 131072

// ======================= scratch (device globals; no allocs allowed) =======================
__device__ __half g_Q16[MQ * DIM];
__device__ __half g_K16[67108864];   // MKV * DIM
__device__ __half g_V16[67108864];
__device__ __half g_xn16[MQ * DIM];
__device__ __half g_lat16[67108864];
__device__ __half g_O16[MQ * DIM];
__device__ __half g_W16[4 * DIM * DIM];   // transposed [n][k]

// ======================= helpers =======================
__device__ __forceinline__ uint32_t smem_u32(const void* p) {
    uint32_t a;
    asm("{ .reg .u64 t; cvta.to.shared.u64 t, %1; cvt.u32.u64 %0, t; }" : "=r"(a) : "l"(p));
    return a;
}

#define CP16(dst, src) \
    asm volatile("cp.async.cg.shared.global [%0], [%1], 16;" :: "r"(dst), "l"(src) : "memory")
#define CP_COMMIT() asm volatile("cp.async.commit_group;" ::: "memory")
#define CP_WAIT2()  asm volatile("cp.async.wait_group 2;" ::: "memory")

__device__ __forceinline__ void ldsm_x4(uint32_t* r, uint32_t addr) {
    asm volatile("ldmatrix.sync.aligned.m8n8.x4.shared.b16 {%0,%1,%2,%3}, [%4];"
                 : "=r"(r[0]), "=r"(r[1]), "=r"(r[2]), "=r"(r[3]) : "r"(addr));
}

__device__ __forceinline__ void mma_f16(float* d, const uint32_t* a, uint32_t b0, uint32_t b1) {
    asm volatile("mma.sync.aligned.m16n8k16.row.col.f32.f16.f16.f32 "
                 "{%0,%1,%2,%3}, {%4,%5,%6,%7}, {%8,%9}, {%0,%1,%2,%3};"
                 : "+f"(d[0]), "+f"(d[1]), "+f"(d[2]), "+f"(d[3])
                 : "r"(a[0]), "r"(a[1]), "r"(a[2]), "r"(a[3]), "r"(b0), "r"(b1));
}

// XOR swizzle: row of 64B = 4 chunks of 16B; chunk ^= (row>>1)&3. Conflict-free for
// ldmatrix 8-row phases and 16B staging (bank enumeration verified).
__device__ __forceinline__ uint32_t swz(int row, int kchunk) {
    return (uint32_t)(row * 64 + ((kchunk ^ ((row >> 1) & 3)) << 4));
}

// ======================= prep: W^T -> fp16 =======================
__global__ void prep_weights(const float* __restrict__ Wq, const float* __restrict__ Wk,
                             const float* __restrict__ Wv, const float* __restrict__ Wo) {
    int idx = blockIdx.x * 256 + threadIdx.x;          // 0 .. 4*512*512-1
    int w = idx >> 18;
    int r = idx & 262143;
    int n = r & 511;
    int k = r >> 9;
    const float* W = (w == 0) ? Wq : (w == 1) ? Wk : (w == 2) ? Wv : Wo;
    g_W16[w * DIM * DIM + n * DIM + k] = __float2half_rn(W[k * DIM + n]);
}

// ======================= latents -> fp16 =======================
__global__ void __launch_bounds__(256) conv_latents(const float* __restrict__ src) {
    size_t base = ((size_t)blockIdx.x * 256 + threadIdx.x) * 8;
    float4 f0 = *(const float4*)(src + base);
    float4 f1 = *(const float4*)(src + base + 4);
    __half2 h[4];
    h[0] = __floats2half2_rn(f0.x, f0.y);
    h[1] = __floats2half2_rn(f0.z, f0.w);
    h[2] = __floats2half2_rn(f1.x, f1.y);
    h[3] = __floats2half2_rn(f1.z, f1.w);
    *(uint4*)(g_lat16 + base) = *(uint4*)h;
}

// ======================= LayerNorm -> fp16 =======================
__global__ void ln_kernel(const float* __restrict__ x, const float* __restrict__ gamma,
                          const float* __restrict__ beta) {
    int warp = threadIdx.x >> 5;
    int lane = threadIdx.x & 31;
    size_t row = (size_t)blockIdx.x * 8 + warp;
    const float* xr = x + row * DIM;
    float4 v[4];
    float s = 0.f, ss = 0.f;
#pragma unroll
    for (int j = 0; j < 4; j++) {
        v[j] = *(const float4*)(xr + j * 128 + lane * 4);
        s  += v[j].x + v[j].y + v[j].z + v[j].w;
        ss += v[j].x * v[j].x + v[j].y * v[j].y + v[j].z * v[j].z + v[j].w * v[j].w;
    }
#pragma unroll
    for (int o = 16; o > 0; o >>= 1) {
        s  += __shfl_xor_sync(0xFFFFFFFFu, s, o);
        ss += __shfl_xor_sync(0xFFFFFFFFu, ss, o);
    }
    float mu  = s * (1.0f / DIM);
    float var = ss * (1.0f / DIM) - mu * mu;
    float inv = rsqrtf(var + 1e-5f);
#pragma unroll
    for (int j = 0; j < 4; j++) {
        int c = j * 128 + lane * 4;
        float4 g = *(const float4*)(gamma + c);
        float4 be = *(const float4*)(beta + c);
        __half2 h[2];
        h[0] = __floats2half2_rn((v[j].x - mu) * inv * g.x + be.x,
                                 (v[j].y - mu) * inv * g.y + be.y);
        h[1] = __floats2half2_rn((v[j].z - mu) * inv * g.z + be.z,
                                 (v[j].w - mu) * inv * g.w + be.w);
        *(uint2*)(g_xn16 + row * DIM + c) = *(uint2*)h;
    }
}

// ======================= GEMM: C[M,512] = A16[M,512] @ W16 + bias (+res) ===========
// single fp16 MMA, cp.async 4-stage, CTA 128x128, BK=32, 256 thr
// register-double-buffered k16 halves: 12 LDSM upfront, then 32 MMAs unbroken
#define BM 128
#define BN 128
#define BK 32
#define OFF_A 0
#define OFF_B 8192
#define STAGE_BYTES 16384
#define NSTAGE 4
#define GEMM_SMEM (NSTAGE * STAGE_BYTES)

__global__ void __launch_bounds__(256, 2) gemm_kernel(
    const __half* __restrict__ A,
    const __half* __restrict__ B1, const float* __restrict__ bias1, void* __restrict__ C1,
    const __half* __restrict__ B2, const float* __restrict__ bias2, void* __restrict__ C2,
    const float* __restrict__ residual, int nx1, int out_half)
{
    extern __shared__ char smc[];
    uint32_t sb = smem_u32(smc);
    const int t = threadIdx.x, lane = t & 31, wid = t >> 5;
    const int wm = wid & 1, wn = wid >> 1;        // warp tile 64(m) x 32(n)
    const int m0 = blockIdx.y * BM;

    const __half* B; const float* bias; void* C;
    int xt = blockIdx.x;
    if (xt < nx1) { B = B1; bias = bias1; C = C1; }
    else          { B = B2; bias = bias2; C = C2; xt -= nx1; }
    const int n0 = xt * BN;

    const int srow = t >> 2, sc = t & 3;          // staging: thread -> (row, 16B chunk)

    auto stage = [&](int s, int k0) {
        uint32_t sbase = sb + (uint32_t)(s & (NSTAGE - 1)) * STAGE_BYTES;
#pragma unroll
        for (int j = 0; j < 2; j++) {
            int row = srow + j * 64;
            uint32_t off = swz(row, sc);
            CP16(sbase + OFF_A + off, A + (size_t)(m0 + row) * DIM + k0 + sc * 8);
            CP16(sbase + OFF_B + off, B + (size_t)(n0 + row) * DIM + k0 + sc * 8);
        }
        CP_COMMIT();
    };

    float acc[4][4][4];
#pragma unroll
    for (int i = 0; i < 4; i++)
#pragma unroll
        for (int j = 0; j < 4; j++)
#pragma unroll
            for (int q = 0; q < 4; q++) acc[i][j][q] = 0.f;

    stage(0, 0);
    stage(1, BK);
    stage(2, 2 * BK);

    const int khalf = lane >> 4;
    for (int s = 0; s < 16; s++) {
        CP_WAIT2();
        __syncthreads();
        if (s + 3 < 16) stage(s + 3, (s + 3) * BK);
        else CP_COMMIT();                          // uniform group accounting
        uint32_t cbase = sb + (uint32_t)(s & (NSTAGE - 1)) * STAGE_BYTES;
        uint32_t Af[2][4][4], Bf[2][2][4];
#pragma unroll
        for (int k16 = 0; k16 < 2; k16++) {
#pragma unroll
            for (int mt = 0; mt < 4; mt++) {
                int row = wm * 64 + mt * 16 + (lane & 15);
                ldsm_x4(Af[k16][mt], cbase + OFF_A + swz(row, k16 * 2 + khalf));
            }
#pragma unroll
            for (int np = 0; np < 2; np++) {
                int row = wn * 32 + np * 16 + (lane & 15);
                ldsm_x4(Bf[k16][np], cbase + OFF_B + swz(row, k16 * 2 + khalf));
            }
        }
#pragma unroll
        for (int k16 = 0; k16 < 2; k16++) {
#pragma unroll
            for (int mt = 0; mt < 4; mt++) {
#pragma unroll
                for (int nt = 0; nt < 4; nt++) {
                    int np = nt >> 1, i = nt & 1;
                    mma_f16(acc[mt][nt], Af[k16][mt], Bf[k16][np][i], Bf[k16][np][i + 2]);
                }
            }
        }
    }

    // ---- epilogue ----
    __syncthreads();
    const int qr = lane >> 2, qc = lane & 3;
#pragma unroll
    for (int mt = 0; mt < 4; mt++) {
#pragma unroll
        for (int nt = 0; nt < 4; nt++) {
            int r = m0 + wm * 64 + mt * 16 + qr;
            int c = n0 + wn * 32 + nt * 8 + qc * 2;
            float b0 = __ldg(bias + c), b1 = __ldg(bias + c + 1);
            float v0 = acc[mt][nt][0] + b0;
            float v1 = acc[mt][nt][1] + b1;
            float v2 = acc[mt][nt][2] + b0;
            float v3 = acc[mt][nt][3] + b1;
            if (out_half) {
                __half* Ch = (__half*)C;
                *(__half2*)(Ch + (size_t)r * DIM + c)       = __floats2half2_rn(v0, v1);
                *(__half2*)(Ch + (size_t)(r + 8) * DIM + c) = __floats2half2_rn(v2, v3);
            } else {
                float* Cf = (float*)C;
                if (residual) {
                    float2 r0 = *(const float2*)(residual + (size_t)r * DIM + c);
                    float2 r1 = *(const float2*)(residual + (size_t)(r + 8) * DIM + c);
                    v0 += r0.x; v1 += r0.y; v2 += r1.x; v3 += r1.y;
                }
                *(float2*)(Cf + (size_t)r * DIM + c)       = make_float2(v0, v1);
                *(float2*)(Cf + (size_t)(r + 8) * DIM + c) = make_float2(v2, v3);
            }
        }
    }
}

// ======================= attention: CTA per (b, h), 128 threads ==================
// Q/K/V fp16 in HBM; fp32 compute. Qs[16][64] + Ps[16][128] smem, conflict-free.
__global__ void __launch_bounds__(128) attn_kernel(
    const __half* __restrict__ Q, const __half* __restrict__ K, const __half* __restrict__ V,
    const float* __restrict__ rel_bias) {
    __shared__ float Qs[16 * 64];
    __shared__ float Ps[16 * 128];
    int t = threadIdx.x;
    int lane = t & 31;
    int bh = blockIdx.x;
    int b = bh >> 3, h = bh & 7;

    {   // load Q tile 16x64 (fp16 -> fp32 smem)
        int q = t >> 3, c = (t & 7) * 8;
        const __half2* Qg = (const __half2*)(Q + ((size_t)(b * LQ + q)) * DIM + h * DH + c);
#pragma unroll
        for (int i = 0; i < 4; i++) {
            float2 f = __half22float2(Qg[i]);
            Qs[q * 64 + c + 2 * i]     = f.x;
            Qs[q * 64 + c + 2 * i + 1] = f.y;
        }
    }
    __syncthreads();

    // ---- scores: thread owns kv = t ----
    {
        const __half2* Kr = (const __half2*)(K + ((size_t)(b * LKV + t)) * DIM + h * DH);
        float acc[16];
#pragma unroll
        for (int q = 0; q < 16; q++) acc[q] = 0.f;
#pragma unroll
        for (int dc = 0; dc < 4; dc++) {
            float kk[16];
#pragma unroll
            for (int i = 0; i < 8; i++) {
                float2 f = __half22float2(Kr[dc * 8 + i]);
                kk[2 * i] = f.x; kk[2 * i + 1] = f.y;
            }
#pragma unroll
            for (int q = 0; q < 16; q++) {
                const float4* qp = (const float4*)(Qs + q * 64 + dc * 16);
#pragma unroll
                for (int i = 0; i < 4; i++) {
                    float4 qv = qp[i];
                    acc[q] += kk[4*i] * qv.x + kk[4*i+1] * qv.y + kk[4*i+2] * qv.z + kk[4*i+3] * qv.w;
                }
            }
        }
        const float* bsrc = rel_bias + ((size_t)h * LQ) * LKV + t;
#pragma unroll
        for (int q = 0; q < 16; q++)
            Ps[q * 128 + t] = acc[q] * 0.125f + bsrc[q * LKV];
    }
    __syncthreads();

    // ---- softmax: warp w handles rows 4w..4w+3 ----
    {
        int w = t >> 5;
#pragma unroll
        for (int qq = 0; qq < 4; qq++) {
            int q = w * 4 + qq;
            float4 pv = *(float4*)(Ps + q * 128 + lane * 4);
            float m = fmaxf(fmaxf(pv.x, pv.y), fmaxf(pv.z, pv.w));
#pragma unroll
            for (int o = 16; o > 0; o >>= 1) m = fmaxf(m, __shfl_xor_sync(0xFFFFFFFFu, m, o));
            pv.x = __expf(pv.x - m); pv.y = __expf(pv.y - m);
            pv.z = __expf(pv.z - m); pv.w = __expf(pv.w - m);
            float s = pv.x + pv.y + pv.z + pv.w;
#pragma unroll
            for (int o = 16; o > 0; o >>= 1) s += __shfl_xor_sync(0xFFFFFFFFu, s, o);
            float inv = 1.0f / s;
            pv.x *= inv; pv.y *= inv; pv.z *= inv; pv.w *= inv;
            *(float4*)(Ps + q * 128 + lane * 4) = pv;
        }
    }
    __syncthreads();

    // ---- PV: thread owns (qhalf = t>>6, d = t&63); out -> fp16 ----
    {
        int d = t & 63, qh = t >> 6;
        const __half* Vb = V + ((size_t)(b * LKV)) * DIM + h * DH + d;
        float o[8];
#pragma unroll
        for (int j = 0; j < 8; j++) o[j] = 0.f;
        for (int kv4 = 0; kv4 < 32; kv4++) {
            float vv0 = __half2float(Vb[(size_t)(kv4 * 4 + 0) * DIM]);
            float vv1 = __half2float(Vb[(size_t)(kv4 * 4 + 1) * DIM]);
            float vv2 = __half2float(Vb[(size_t)(kv4 * 4 + 2) * DIM]);
            float vv3 = __half2float(Vb[(size_t)(kv4 * 4 + 3) * DIM]);
#pragma unroll
            for (int j = 0; j < 8; j++) {
                float4 p = *(float4*)(Ps + (qh * 8 + j) * 128 + kv4 * 4);
                o[j] += p.x * vv0 + p.y * vv1 + p.z * vv2 + p.w * vv3;
            }
        }
#pragma unroll
        for (int j = 0; j < 8; j++) {
            size_t row = (size_t)(b * LQ + qh * 8 + j);
            g_O16[row * DIM + h * DH + d] = __float2half_rn(o[j]);
        }
    }
}

// ======================= launch =======================
extern "C" void kernel_launch(void* const* d_in, const int* in_sizes, int n_in,
                              void* d_out, int out_size) {
    const float* x       = (const float*)d_in[0];
    const float* latents = (const float*)d_in[1];
    const float* Wq = (const float*)d_in[2];
    const float* bq = (const float*)d_in[3];
    const float* Wk = (const float*)d_in[4];
    const float* bk = (const float*)d_in[5];
    const float* Wv = (const float*)d_in[6];
    const float* bv = (const float*)d_in[7];
    const float* Wo = (const float*)d_in[8];
    const float* bo = (const float*)d_in[9];
    const float* gamma = (const float*)d_in[10];
    const float* beta  = (const float*)d_in[11];
    const float* rel   = (const float*)d_in[12];
    float* out = (float*)d_out;

    void *pQ, *pK, *pV, *pw, *pxn, *plat, *po16;
    cudaGetSymbolAddress(&pQ, g_Q16);
    cudaGetSymbolAddress(&pK, g_K16);
    cudaGetSymbolAddress(&pV, g_V16);
    cudaGetSymbolAddress(&pw, g_W16);
    cudaGetSymbolAddress(&pxn, g_xn16);
    cudaGetSymbolAddress(&plat, g_lat16);
    cudaGetSymbolAddress(&po16, g_O16);
    const __half* w16 = (const __half*)pw;

    cudaFuncSetAttribute(gemm_kernel, cudaFuncAttributeMaxDynamicSharedMemorySize, GEMM_SMEM);

    prep_weights<<<4096, 256>>>(Wq, Wk, Wv, Wo);
    ln_kernel<<<MQ / 8, 256>>>(x, gamma, beta);
    conv_latents<<<(MKV * DIM) / (256 * 8), 256>>>(latents);

    // Q = LN(x) @ Wq + bq  -> fp16
    gemm_kernel<<<dim3(4, MQ / 128), 256, GEMM_SMEM>>>(
        (const __half*)pxn,
        w16 + 0 * DIM * DIM, bq, pQ,
        w16 + 0 * DIM * DIM, bq, pQ,
        nullptr, 4, 1);

    // K|V = latents @ {Wk|Wv} -> fp16: grid.x = 8 (0-3 -> K, 4-7 -> V)
    gemm_kernel<<<dim3(8, MKV / 128), 256, GEMM_SMEM>>>(
        (const __half*)plat,
        w16 + 1 * DIM * DIM, bk, pK,
        w16 + 2 * DIM * DIM, bv, pV,
        nullptr, 4, 1);

    attn_kernel<<<B_SZ * NH, 128>>>(
        (const __half*)pQ, (const __half*)pK, (const __half*)pV, rel);

    // out = x + (attn_out @ Wo + bo)  -> fp32
    gemm_kernel<<<dim3(4, MQ / 128), 256, GEMM_SMEM>>>(
        (const __half*)po16,
        w16 + 3 * DIM * DIM, bo, out,
        w16 + 3 * DIM * DIM, bo, out,
        x, 4, 0);
}